// round 15
// baseline (speedup 1.0000x reference)
#include <cuda_runtime.h>
#include <cuda_fp16.h>
#include <cstdint>

#define N_NODES 200000
#define DEG 16
#define T_ROUNDS 3
#define HDIM 70
#define HSTRIDE 72
#define NKT 10              // K padded to 160 = 10 * 16
#define NB 72
#define WARPS 9
#define THREADS 288
#define BMT 29              // m-tiles (16 nodes) per block
#define BM (BMT * 16)       // 464 nodes per block
#define NBLK 432            // one wave
#define SH 84               // A smem row stride in words (336B; ldmatrix conflict-free)
#define IMGW (16 * SH)      // 1344 words per image

#define RBLOCKS 1024
#define RTHREADS 128

// ---------------- device scratch (static: no allocation) ----------------
__device__ float    g_h[2][N_NODES * HSTRIDE];
__device__ float    g_me6T[DEG][N_NODES * 6];
__device__ int      g_nbrT[DEG][N_NODES];
__device__ float    g_Wtmp[160 * NB];
__device__ uint32_t g_Bfhi[WARPS * NKT * 2 * 32];
__device__ uint32_t g_Bflo[WARPS * NKT * 2 * 32];
__device__ float    g_btot[NB];
__device__ float    g_Rc[HDIM * 128];
__device__ float    g_partial[RBLOCKS * 128];

// ---------------- helpers ----------------
__device__ __forceinline__ uint32_t pack_h2(__half a, __half b) {
    __half2 t = __halves2half2(a, b);
    return *(uint32_t*)&t;
}
__device__ __forceinline__ uint32_t h2u(__half2 h) { return *(uint32_t*)&h; }

#define MMA16(C,a0,a1,a2,a3,b0,b1)                                           \
    asm volatile("mma.sync.aligned.m16n8k16.row.col.f32.f16.f16.f32 "        \
        "{%0,%1,%2,%3}, {%4,%5,%6,%7}, {%8,%9}, {%0,%1,%2,%3};"              \
        : "+f"(C[0]), "+f"(C[1]), "+f"(C[2]), "+f"(C[3])                     \
        : "r"(a0), "r"(a1), "r"(a2), "r"(a3), "r"(b0), "r"(b1))

#define LDSM4(R, addr)                                                       \
    asm volatile("ldmatrix.sync.aligned.m8n8.x4.shared.b16 {%0,%1,%2,%3}, [%4];" \
        : "=r"((R)[0]), "=r"((R)[1]), "=r"((R)[2]), "=r"((R)[3]) : "r"(addr))

// ---------------- prep 1: folded weight matrix (multi-block) ----------------
// K-slot map: k in [0,70)=U1 ; [72,142)=(Vw@U2) ; [144,150)=U3 ; else 0.
__global__ void prep1_kernel(const float* __restrict__ Vw,
                             const float* __restrict__ Uw) {
    for (int i = blockIdx.x * blockDim.x + threadIdx.x; i < 160 * NB;
         i += gridDim.x * blockDim.x) {
        int k = i / NB, n = i % NB;
        float w = 0.f;
        if (n < HDIM) {
            if (k < 70) {
                w = Uw[k * HDIM + n];
            } else if (k >= 72 && k < 142) {
                int p = k - 72;
                float s = 0.f;
                for (int q = 0; q < 70; ++q) s += Vw[p * 70 + q] * Uw[(70 + q) * HDIM + n];
                w = s;
            } else if (k >= 144 && k < 150) {
                w = Uw[(140 + (k - 144)) * HDIM + n];
            }
        }
        g_Wtmp[i] = w;
    }
}

// ---------------- prep 2: fragments, bias, readout weights ----------------
__global__ void prep2_kernel(const float* __restrict__ Vb,
                             const float* __restrict__ Uw, const float* __restrict__ Ub,
                             const float* __restrict__ Rw) {
    int stride = gridDim.x * blockDim.x;
    int tid0 = blockIdx.x * blockDim.x + threadIdx.x;
    // B fragment (m16n8k16): idx = ((w*NKT + kt)*2 + r)*32 + lane
    for (int idx = tid0; idx < WARPS * NKT * 2 * 32; idx += stride) {
        int lane = idx & 31;
        int t = idx >> 5;
        int r = t & 1; t >>= 1;
        int kt = t % NKT;
        int w = t / NKT;
        int k0 = kt * 16 + (lane & 3) * 2 + 8 * r;
        int n = w * 8 + (lane >> 2);
        float v0 = g_Wtmp[k0 * NB + n];
        float v1 = g_Wtmp[(k0 + 1) * NB + n];
        __half h0 = __float2half_rn(v0), h1 = __float2half_rn(v1);
        g_Bfhi[idx] = pack_h2(h0, h1);
        g_Bflo[idx] = pack_h2(__float2half_rn(v0 - __half2float(h0)),
                              __float2half_rn(v1 - __half2float(h1)));
    }
    for (int k = tid0; k < NB; k += stride) {
        float v = 0.f;
        if (k < HDIM) {
            v = Ub[k];
            for (int q = 0; q < 70; ++q) v += Vb[q] * Uw[(70 + q) * HDIM + k];
        }
        g_btot[k] = v;
    }
    for (int i = tid0; i < HDIM * 128; i += stride) {
        int p = i / 128, k = i % 128;
        g_Rc[i] = Rw[p * 128 + k] + Rw[(70 + p) * 128 + k];
    }
}

// ---------------- edge messages -> slice-major; nbr transpose ----------------
__global__ void edge_kernel(const float* __restrict__ ef,
                            const float* __restrict__ Ew,
                            const float* __restrict__ Eb,
                            const int* __restrict__ nbr) {
    int i = blockIdx.x * blockDim.x + threadIdx.x;
    if (i >= N_NODES * DEG) return;
    int node = i / DEG, j = i % DEG;
    float e[6];
#pragma unroll
    for (int d = 0; d < 6; ++d) e[d] = ef[i * 6 + d];
#pragma unroll
    for (int c = 0; c < 6; ++c) {
        float s = __ldg(&Eb[c]);
#pragma unroll
        for (int d = 0; d < 6; ++d) s += e[d] * __ldg(&Ew[d * 6 + c]);
        g_me6T[j][node * 6 + c] = s;
    }
    g_nbrT[j][node] = nbr[i];
}

__global__ void init_kernel(const float* __restrict__ h) {
    int i = blockIdx.x * blockDim.x + threadIdx.x;
    if (i >= N_NODES * HSTRIDE) return;
    int v = i / HSTRIDE, k = i % HSTRIDE;
    g_h[0][i] = (k < HDIM) ? h[v * HDIM + k] : 0.f;
}

// ---------------- split fill: LDG phase (regs) + STS phase (smem) ----------------
// Chunk e of m-tile: r = e/40 (row), q = e%40 (float4 within padded-160 cols).
// cols: self [0,72) | gather [72,144) | me [144,150) | pad [150,160)
__device__ __forceinline__ float4 ldg_chunk(const float* __restrict__ hin,
                                            const int* __restrict__ sg,
                                            const float* __restrict__ mej,
                                            int base, int mt, int r, int q) {
    int node = base + mt * 16 + r;
    if (node > N_NODES - 1) node = N_NODES - 1;
    if (q < 18) {
        return *(const float4*)(hin + (size_t)node * HSTRIDE + 4 * q);
    } else if (q < 36) {
        int gi = sg[mt * 16 + r];
        return *(const float4*)(hin + (size_t)gi * HSTRIDE + 4 * (q - 18));
    } else if (q == 36) {
        const float* me = mej + (size_t)node * 6;
        float2 a = *(const float2*)me;
        float2 b = *(const float2*)(me + 2);
        return make_float4(a.x, a.y, b.x, b.y);
    } else if (q == 37) {
        const float* me = mej + (size_t)node * 6;
        float2 c = *(const float2*)(me + 4);
        return make_float4(c.x, c.y, 0.f, 0.f);
    }
    return make_float4(0.f, 0.f, 0.f, 0.f);   // pad
}

// A smem layout: row-linear fp16, hi at [0, IMGW), lo at +IMGW.
__device__ __forceinline__ void sts_chunk(uint32_t* __restrict__ a, int r, int q, float4 v) {
    int base = r * SH + 2 * q;
    __half2 h01 = __float22half2_rn(make_float2(v.x, v.y));
    __half2 h23 = __float22half2_rn(make_float2(v.z, v.w));
    float2 f01 = __half22float2(h01);
    float2 f23 = __half22float2(h23);
    __half2 l01 = __float22half2_rn(make_float2(v.x - f01.x, v.y - f01.y));
    __half2 l23 = __float22half2_rn(make_float2(v.z - f23.x, v.w - f23.y));
    *(uint2*)(a + base)        = make_uint2(h2u(h01), h2u(h23));
    *(uint2*)(a + IMGW + base) = make_uint2(h2u(l01), h2u(l23));
}

// ---------------- one MP step on tensor cores (fp16 3-term split) ----------------
__global__ __launch_bounds__(THREADS, 3)
void step_kernel(int j, int src) {
    __shared__ uint32_t sA[3][2 * IMGW];      // 3-deep rotation [hi | lo]
    __shared__ int s_gidx[BM];

    const float* __restrict__ hin = g_h[src];
    float* __restrict__ hout = g_h[src ^ 1];
    const int* __restrict__ nbrj = g_nbrT[j];
    const float* __restrict__ mej = g_me6T[j];
    int tid = threadIdx.x, w = tid >> 5, lane = tid & 31;
    int base = blockIdx.x * BM;

    // B fragments: 40 regs (once per block)
    uint32_t Bhi[NKT][2], Blo[NKT][2];
#pragma unroll
    for (int kt = 0; kt < NKT; ++kt)
#pragma unroll
        for (int r = 0; r < 2; ++r) {
            int idx = ((w * NKT + kt) * 2 + r) * 32 + lane;
            Bhi[kt][r] = g_Bfhi[idx];
            Blo[kt][r] = g_Bflo[idx];
        }
    int col = w * 8 + (lane & 3) * 2;
    float bb0 = g_btot[col], bb1 = g_btot[col + 1];

    // gather indices for all nodes of this block
    for (int i = tid; i < BM; i += THREADS) {
        int node = base + i;
        if (node > N_NODES - 1) node = N_NODES - 1;
        s_gidx[i] = __ldg(&nbrj[node]);
    }
    __syncthreads();

    // per-thread chunk ownership: 640 chunks per m-tile
    const int e0 = tid, e1 = tid + THREADS;
    const int r0 = e0 / 40, q0 = e0 - r0 * 40;
    const int r1 = e1 / 40, q1 = e1 - r1 * 40;
    const bool has2 = (tid < 16 * 40 - 2 * THREADS);   // 64 threads
    const int e2 = tid + 2 * THREADS;
    const int r2 = e2 / 40, q2 = e2 - r2 * 40;

    float4 v0, v1, v2;
    // prologue: fill tile 0; preload tile 1 into vregs
    {
        float4 p0 = ldg_chunk(hin, s_gidx, mej, base, 0, r0, q0);
        float4 p1 = ldg_chunk(hin, s_gidx, mej, base, 0, r1, q1);
        float4 p2 = has2 ? ldg_chunk(hin, s_gidx, mej, base, 0, r2, q2)
                         : make_float4(0.f, 0.f, 0.f, 0.f);
        sts_chunk(sA[0], r0, q0, p0);
        sts_chunk(sA[0], r1, q1, p1);
        if (has2) sts_chunk(sA[0], r2, q2, p2);
        v0 = ldg_chunk(hin, s_gidx, mej, base, 1, r0, q0);
        v1 = ldg_chunk(hin, s_gidx, mej, base, 1, r1, q1);
        if (has2) v2 = ldg_chunk(hin, s_gidx, mej, base, 1, r2, q2);
    }
    __syncthreads();

    // ldmatrix lane address
    const int lrow = (lane & 7) + 8 * ((lane >> 3) & 1);
    const int loff = (lrow * SH + ((lane >> 4) & 1) * 4) * 4;   // bytes
    uint32_t sb[3];
    sb[0] = (uint32_t)__cvta_generic_to_shared(sA[0]);
    sb[1] = (uint32_t)__cvta_generic_to_shared(sA[1]);
    sb[2] = (uint32_t)__cvta_generic_to_shared(sA[2]);

    int cur = 0;   // buffer of tile mt
#pragma unroll 1
    for (int mt = 0; mt < BMT; ++mt) {
        int nxt = (cur == 2) ? 0 : cur + 1;

        // (1) store tile mt+1 from vregs (loaded a full iteration ago)
        if (mt < BMT - 1) {
            uint32_t* na = sA[nxt];
            sts_chunk(na, r0, q0, v0);
            sts_chunk(na, r1, q1, v1);
            if (has2) sts_chunk(na, r2, q2, v2);
        }
        // (2) issue LDGs for tile mt+2 (consumed next iteration -> full cover)
        if (mt < BMT - 2) {
            v0 = ldg_chunk(hin, s_gidx, mej, base, mt + 2, r0, q0);
            v1 = ldg_chunk(hin, s_gidx, mej, base, mt + 2, r1, q1);
            if (has2) v2 = ldg_chunk(hin, s_gidx, mej, base, mt + 2, r2, q2);
        }

        // (3) compute tile mt
        const uint32_t ahi = sb[cur] + loff;
        const uint32_t alo = ahi + IMGW * 4;
        float ch[4] = {0.f, 0.f, 0.f, 0.f};
        float cc[4] = {0.f, 0.f, 0.f, 0.f};
#pragma unroll
        for (int kt = 0; kt < NKT; ++kt) {
            uint32_t A[4], L[4];
            LDSM4(A, ahi + kt * 32);
            LDSM4(L, alo + kt * 32);
            MMA16(ch, A[0], A[1], A[2], A[3], Bhi[kt][0], Bhi[kt][1]);
            MMA16(cc, A[0], A[1], A[2], A[3], Blo[kt][0], Blo[kt][1]);
            MMA16(cc, L[0], L[1], L[2], L[3], Bhi[kt][0], Bhi[kt][1]);
        }

        // (4) epilogue: bias + relu, store two float2 per thread
        int row = lane >> 2;
        int node0 = base + mt * 16 + row;
        if (node0 < N_NODES) {
            float2 o;
            o.x = fmaxf((ch[0] + cc[0]) + bb0, 0.f);
            o.y = fmaxf((ch[1] + cc[1]) + bb1, 0.f);
            *(float2*)(hout + (size_t)node0 * HSTRIDE + col) = o;
        }
        int node1 = node0 + 8;
        if (node1 < N_NODES) {
            float2 o;
            o.x = fmaxf((ch[2] + cc[2]) + bb0, 0.f);
            o.y = fmaxf((ch[3] + cc[3]) + bb1, 0.f);
            *(float2*)(hout + (size_t)node1 * HSTRIDE + col) = o;
        }
        __syncthreads();
        cur = nxt;
    }
}

// ---------------- readout ----------------
__global__ __launch_bounds__(RTHREADS)
void readout_kernel(const float* __restrict__ Rb) {
    int k = threadIdx.x;
    float rc[HSTRIDE];
#pragma unroll
    for (int p = 0; p < HDIM; ++p) rc[p] = g_Rc[p * 128 + k];
    rc[70] = 0.f; rc[71] = 0.f;
    float rb = Rb[k];

    int per = (N_NODES + RBLOCKS - 1) / RBLOCKS;
    int n0 = blockIdx.x * per;
    int n1 = n0 + per; if (n1 > N_NODES) n1 = N_NODES;

    float acc = 0.f;
    for (int n = n0; n < n1; ++n) {
        const float4* hp = (const float4*)(g_h[0] + (size_t)n * HSTRIDE);
        float s = rb;
#pragma unroll
        for (int q = 0; q < HSTRIDE / 4; ++q) {
            float4 hv = __ldg(&hp[q]);
            s += hv.x * rc[4 * q] + hv.y * rc[4 * q + 1]
               + hv.z * rc[4 * q + 2] + hv.w * rc[4 * q + 3];
        }
        acc += fmaxf(s, 0.f);
    }
    g_partial[blockIdx.x * 128 + k] = acc;
}

__global__ void final_kernel(const float* __restrict__ S1w, const float* __restrict__ S1b,
                             const float* __restrict__ S2w, const float* __restrict__ S2b,
                             const float* __restrict__ Hw,  const float* __restrict__ Hb,
                             const float* __restrict__ Ow,  const float* __restrict__ Ob,
                             float* __restrict__ out) {
    __shared__ float fm[128], av[128], bv[100], cv[100];
    int t = threadIdx.x;
    float s = 0.f;
    for (int b = 0; b < RBLOCKS; ++b) s += g_partial[b * 128 + t];
    fm[t] = s;
    __syncthreads();
    float v = S1b[t];
    for (int p = 0; p < 128; ++p) v += fm[p] * S1w[p * 128 + t];
    av[t] = fmaxf(v, 0.f);
    __syncthreads();
    if (t < 100) {
        v = S2b[t];
        for (int p = 0; p < 128; ++p) v += av[p] * S2w[p * 100 + t];
        bv[t] = v;
    }
    __syncthreads();
    if (t < 100) {
        v = Hb[t];
        for (int p = 0; p < 100; ++p) v += bv[p] * Hw[p * 100 + t];
        cv[t] = fmaxf(v, 0.f);
    }
    __syncthreads();
    if (t == 0) {
        v = Ob[0];
        for (int p = 0; p < 100; ++p) v += cv[p] * Ow[p];
        out[0] = v;
    }
}

extern "C" void kernel_launch(void* const* d_in, const int* in_sizes, int n_in,
                              void* d_out, int out_size) {
    const float* h   = (const float*)d_in[0];
    const float* ef  = (const float*)d_in[1];
    const int*   nbr = (const int*)d_in[2];
    const float* Vw  = (const float*)d_in[3];
    const float* Vb  = (const float*)d_in[4];
    const float* Ew  = (const float*)d_in[5];
    const float* Eb  = (const float*)d_in[6];
    const float* Uw  = (const float*)d_in[7];
    const float* Ub  = (const float*)d_in[8];
    const float* Rw  = (const float*)d_in[9];
    const float* Rb  = (const float*)d_in[10];
    const float* S1w = (const float*)d_in[11];
    const float* S1b = (const float*)d_in[12];
    const float* S2w = (const float*)d_in[13];
    const float* S2b = (const float*)d_in[14];
    const float* Hw  = (const float*)d_in[15];
    const float* Hb  = (const float*)d_in[16];
    const float* Ow  = (const float*)d_in[17];
    const float* Ob  = (const float*)d_in[18];
    float* out = (float*)d_out;

    prep1_kernel<<<45, 256>>>(Vw, Uw);
    prep2_kernel<<<40, 256>>>(Vb, Uw, Ub, Rw);
    edge_kernel<<<(N_NODES * DEG + 255) / 256, 256>>>(ef, Ew, Eb, nbr);
    init_kernel<<<(N_NODES * HSTRIDE + 255) / 256, 256>>>(h);

    int src = 0;
    for (int r = 0; r < T_ROUNDS; ++r) {
        for (int j = 0; j < DEG; ++j) {
            step_kernel<<<NBLK, THREADS>>>(j, src);
            src ^= 1;
        }
    }
    // 48 steps (even) -> final state in g_h[0]
    readout_kernel<<<RBLOCKS, RTHREADS>>>(Rb);
    final_kernel<<<1, 128>>>(S1w, S1b, S2w, S2b, Hw, Hb, Ow, Ob, out);
}

// round 16
// speedup vs baseline: 1.1850x; 1.1850x over previous
#include <cuda_runtime.h>
#include <cuda_fp16.h>
#include <cstdint>

#define N_NODES 200000
#define DEG 16
#define T_ROUNDS 3
#define HDIM 70
#define HSTRIDE 72
#define NKT 10              // step K padded to 160 = 10 * 16
#define NB 72
#define WARPS 9
#define THREADS 288
#define BMT 29              // m-tiles (16 nodes) per block
#define BM (BMT * 16)       // 464 nodes per block
#define NBLK 432            // one wave
#define SH 84               // step A smem row stride in words (336B; ldmatrix conflict-free)
#define IMGW (16 * SH)

// readout (tensorized)
#define RNKT 5              // K = 70 padded to 80 = 5 * 16
#define RWARPS 16
#define RTHREADS 512
#define SHR 44              // readout A row stride in words (176B; 176%128=48 -> conflict-free)
#define IMGWR (16 * SHR)

// fused setup partition
#define EDGE_BLKS 12500     // ceil(3.2M / 256)
#define INIT_BLKS 28125     // 200000*36 / 256 exactly
#define PREP_BLKS 45        // 160*72 = 11520 = 45*256 exactly

// ---------------- device scratch (static: no allocation) ----------------
__device__ float    g_h[2][N_NODES * HSTRIDE];
__device__ float    g_me6T[DEG][N_NODES * 6];
__device__ int      g_nbrT[DEG][N_NODES];
__device__ float    g_Wtmp[160 * NB];
__device__ uint32_t g_Bfhi[WARPS * NKT * 2 * 32];
__device__ uint32_t g_Bflo[WARPS * NKT * 2 * 32];
__device__ uint32_t g_Rfhi[RWARPS * RNKT * 2 * 32];
__device__ uint32_t g_Rflo[RWARPS * RNKT * 2 * 32];
__device__ float    g_btot[NB];
__device__ float    g_partial[NBLK * 128];

// ---------------- helpers ----------------
__device__ __forceinline__ uint32_t pack_h2(__half a, __half b) {
    __half2 t = __halves2half2(a, b);
    return *(uint32_t*)&t;
}
__device__ __forceinline__ uint32_t h2u(__half2 h) { return *(uint32_t*)&h; }

#define MMA16(C,a0,a1,a2,a3,b0,b1)                                           \
    asm volatile("mma.sync.aligned.m16n8k16.row.col.f32.f16.f16.f32 "        \
        "{%0,%1,%2,%3}, {%4,%5,%6,%7}, {%8,%9}, {%0,%1,%2,%3};"              \
        : "+f"(C[0]), "+f"(C[1]), "+f"(C[2]), "+f"(C[3])                     \
        : "r"(a0), "r"(a1), "r"(a2), "r"(a3), "r"(b0), "r"(b1))

#define LDSM4(R, addr)                                                       \
    asm volatile("ldmatrix.sync.aligned.m8n8.x4.shared.b16 {%0,%1,%2,%3}, [%4];" \
        : "=r"((R)[0]), "=r"((R)[1]), "=r"((R)[2]), "=r"((R)[3]) : "r"(addr))

// ---------------- fused setup: edge msgs + init h + folded W (prep1) ----------------
// K-slot map: k in [0,70)=U1 ; [72,142)=(Vw@U2) ; [144,150)=U3 ; else 0.
__global__ void setup_kernel(const float* __restrict__ ef,
                             const float* __restrict__ Ew,
                             const float* __restrict__ Eb,
                             const int* __restrict__ nbr,
                             const float* __restrict__ h,
                             const float* __restrict__ Vw,
                             const float* __restrict__ Uw) {
    int b = blockIdx.x;
    if (b < EDGE_BLKS) {
        int i = b * 256 + threadIdx.x;
        if (i >= N_NODES * DEG) return;
        int node = i / DEG, j = i % DEG;
        float e[6];
#pragma unroll
        for (int d = 0; d < 6; ++d) e[d] = ef[i * 6 + d];
#pragma unroll
        for (int c = 0; c < 6; ++c) {
            float s = __ldg(&Eb[c]);
#pragma unroll
            for (int d = 0; d < 6; ++d) s += e[d] * __ldg(&Ew[d * 6 + c]);
            g_me6T[j][node * 6 + c] = s;
        }
        g_nbrT[j][node] = nbr[i];
    } else if (b < EDGE_BLKS + INIT_BLKS) {
        int i = (b - EDGE_BLKS) * 256 + threadIdx.x;   // over N_NODES*36 float2 slots
        int v = i / 36, k2 = i % 36;
        float2 o = make_float2(0.f, 0.f);
        if (k2 < 35) o = *(const float2*)(h + (size_t)v * HDIM + 2 * k2);
        *(float2*)(g_h[0] + (size_t)v * HSTRIDE + 2 * k2) = o;
    } else {
        int i = (b - EDGE_BLKS - INIT_BLKS) * 256 + threadIdx.x;   // over 160*NB
        int k = i / NB, n = i % NB;
        float w = 0.f;
        if (n < HDIM) {
            if (k < 70) {
                w = Uw[k * HDIM + n];
            } else if (k >= 72 && k < 142) {
                int p = k - 72;
                float s = 0.f;
                for (int q = 0; q < 70; ++q) s += Vw[p * 70 + q] * Uw[(70 + q) * HDIM + n];
                w = s;
            } else if (k >= 144 && k < 150) {
                w = Uw[(140 + (k - 144)) * HDIM + n];
            }
        }
        g_Wtmp[i] = w;
    }
}

// ---------------- prep2: step + readout fragment images, bias ----------------
__global__ void prep2_kernel(const float* __restrict__ Vb,
                             const float* __restrict__ Uw, const float* __restrict__ Ub,
                             const float* __restrict__ Rw) {
    int stride = gridDim.x * blockDim.x;
    int tid0 = blockIdx.x * blockDim.x + threadIdx.x;
    // step B fragments
    for (int idx = tid0; idx < WARPS * NKT * 2 * 32; idx += stride) {
        int lane = idx & 31;
        int t = idx >> 5;
        int r = t & 1; t >>= 1;
        int kt = t % NKT;
        int w = t / NKT;
        int k0 = kt * 16 + (lane & 3) * 2 + 8 * r;
        int n = w * 8 + (lane >> 2);
        float v0 = g_Wtmp[k0 * NB + n];
        float v1 = g_Wtmp[(k0 + 1) * NB + n];
        __half h0 = __float2half_rn(v0), h1 = __float2half_rn(v1);
        g_Bfhi[idx] = pack_h2(h0, h1);
        g_Bflo[idx] = pack_h2(__float2half_rn(v0 - __half2float(h0)),
                              __float2half_rn(v1 - __half2float(h1)));
    }
    // readout fragments: Rc[k][n] = Rw[k*128+n] + Rw[(70+k)*128+n], k<70 else 0
    for (int idx = tid0; idx < RWARPS * RNKT * 2 * 32; idx += stride) {
        int lane = idx & 31;
        int t = idx >> 5;
        int r = t & 1; t >>= 1;
        int kt = t % RNKT;
        int w = t / RNKT;
        int k0 = kt * 16 + (lane & 3) * 2 + 8 * r;
        int n = w * 8 + (lane >> 2);
        float v0 = (k0 < HDIM) ? (Rw[k0 * 128 + n] + Rw[(70 + k0) * 128 + n]) : 0.f;
        float v1 = (k0 + 1 < HDIM) ? (Rw[(k0 + 1) * 128 + n] + Rw[(71 + k0) * 128 + n]) : 0.f;
        __half h0 = __float2half_rn(v0), h1 = __float2half_rn(v1);
        g_Rfhi[idx] = pack_h2(h0, h1);
        g_Rflo[idx] = pack_h2(__float2half_rn(v0 - __half2float(h0)),
                              __float2half_rn(v1 - __half2float(h1)));
    }
    for (int k = tid0; k < NB; k += stride) {
        float v = 0.f;
        if (k < HDIM) {
            v = Ub[k];
            for (int q = 0; q < 70; ++q) v += Vb[q] * Uw[(70 + q) * HDIM + k];
        }
        g_btot[k] = v;
    }
}

// ---------------- step fill helpers (R14, unchanged) ----------------
__device__ __forceinline__ float4 ldg_chunk(const float* __restrict__ hin,
                                            const int* __restrict__ sg,
                                            const float* __restrict__ mej,
                                            int base, int mt, int r, int q) {
    int node = base + mt * 16 + r;
    if (node > N_NODES - 1) node = N_NODES - 1;
    if (q < 18) {
        return *(const float4*)(hin + (size_t)node * HSTRIDE + 4 * q);
    } else if (q < 36) {
        int gi = sg[mt * 16 + r];
        return *(const float4*)(hin + (size_t)gi * HSTRIDE + 4 * (q - 18));
    } else if (q == 36) {
        const float* me = mej + (size_t)node * 6;
        float2 a = *(const float2*)me;
        float2 b = *(const float2*)(me + 2);
        return make_float4(a.x, a.y, b.x, b.y);
    } else if (q == 37) {
        const float* me = mej + (size_t)node * 6;
        float2 c = *(const float2*)(me + 4);
        return make_float4(c.x, c.y, 0.f, 0.f);
    }
    return make_float4(0.f, 0.f, 0.f, 0.f);
}

__device__ __forceinline__ void sts_chunk(uint32_t* __restrict__ a, int r, int q, float4 v) {
    int base = r * SH + 2 * q;
    __half2 h01 = __float22half2_rn(make_float2(v.x, v.y));
    __half2 h23 = __float22half2_rn(make_float2(v.z, v.w));
    float2 f01 = __half22float2(h01);
    float2 f23 = __half22float2(h23);
    __half2 l01 = __float22half2_rn(make_float2(v.x - f01.x, v.y - f01.y));
    __half2 l23 = __float22half2_rn(make_float2(v.z - f23.x, v.w - f23.y));
    *(uint2*)(a + base)        = make_uint2(h2u(h01), h2u(h23));
    *(uint2*)(a + IMGW + base) = make_uint2(h2u(l01), h2u(l23));
}

// ---------------- one MP step (R14-proven pipeline) ----------------
__global__ __launch_bounds__(THREADS, 3)
void step_kernel(int j, int src) {
    __shared__ uint32_t sA[2][2 * IMGW];
    __shared__ int s_gidx[BM];

    const float* __restrict__ hin = g_h[src];
    float* __restrict__ hout = g_h[src ^ 1];
    const int* __restrict__ nbrj = g_nbrT[j];
    const float* __restrict__ mej = g_me6T[j];
    int tid = threadIdx.x, w = tid >> 5, lane = tid & 31;
    int base = blockIdx.x * BM;

    uint32_t Bhi[NKT][2], Blo[NKT][2];
#pragma unroll
    for (int kt = 0; kt < NKT; ++kt)
#pragma unroll
        for (int r = 0; r < 2; ++r) {
            int idx = ((w * NKT + kt) * 2 + r) * 32 + lane;
            Bhi[kt][r] = g_Bfhi[idx];
            Blo[kt][r] = g_Bflo[idx];
        }
    int col = w * 8 + (lane & 3) * 2;
    float bb0 = g_btot[col], bb1 = g_btot[col + 1];

    for (int i = tid; i < BM; i += THREADS) {
        int node = base + i;
        if (node > N_NODES - 1) node = N_NODES - 1;
        s_gidx[i] = __ldg(&nbrj[node]);
    }
    __syncthreads();

    const int e0 = tid, e1 = tid + THREADS;
    const int r0 = e0 / 40, q0 = e0 - r0 * 40;
    const int r1 = e1 / 40, q1 = e1 - r1 * 40;
    const bool has2 = (tid < 16 * 40 - 2 * THREADS);
    const int e2 = tid + 2 * THREADS;
    const int r2 = e2 / 40, q2 = e2 - r2 * 40;

    {
        float4 v0 = ldg_chunk(hin, s_gidx, mej, base, 0, r0, q0);
        float4 v1 = ldg_chunk(hin, s_gidx, mej, base, 0, r1, q1);
        float4 v2 = has2 ? ldg_chunk(hin, s_gidx, mej, base, 0, r2, q2)
                         : make_float4(0.f, 0.f, 0.f, 0.f);
        sts_chunk(sA[0], r0, q0, v0);
        sts_chunk(sA[0], r1, q1, v1);
        if (has2) sts_chunk(sA[0], r2, q2, v2);
    }
    __syncthreads();

    const int lrow = (lane & 7) + 8 * ((lane >> 3) & 1);
    const int loff = (lrow * SH + ((lane >> 4) & 1) * 4) * 4;
    const uint32_t sb0 = (uint32_t)__cvta_generic_to_shared(sA[0]);
    const uint32_t sb1 = (uint32_t)__cvta_generic_to_shared(sA[1]);

#pragma unroll 1
    for (int mt = 0; mt < BMT; ++mt) {
        float4 v0, v1, v2;
        if (mt < BMT - 1) {
            v0 = ldg_chunk(hin, s_gidx, mej, base, mt + 1, r0, q0);
            v1 = ldg_chunk(hin, s_gidx, mej, base, mt + 1, r1, q1);
            if (has2) v2 = ldg_chunk(hin, s_gidx, mej, base, mt + 1, r2, q2);
        }

        const uint32_t ahi = ((mt & 1) ? sb1 : sb0) + loff;
        const uint32_t alo = ahi + IMGW * 4;
        float ch[4] = {0.f, 0.f, 0.f, 0.f};
        float cc[4] = {0.f, 0.f, 0.f, 0.f};
#pragma unroll
        for (int kt = 0; kt < NKT; ++kt) {
            uint32_t A[4], L[4];
            LDSM4(A, ahi + kt * 32);
            LDSM4(L, alo + kt * 32);
            MMA16(ch, A[0], A[1], A[2], A[3], Bhi[kt][0], Bhi[kt][1]);
            MMA16(cc, A[0], A[1], A[2], A[3], Blo[kt][0], Blo[kt][1]);
            MMA16(cc, L[0], L[1], L[2], L[3], Bhi[kt][0], Bhi[kt][1]);
        }

        if (mt < BMT - 1) {
            uint32_t* na = sA[(mt + 1) & 1];
            sts_chunk(na, r0, q0, v0);
            sts_chunk(na, r1, q1, v1);
            if (has2) sts_chunk(na, r2, q2, v2);
        }

        int row = lane >> 2;
        int node0 = base + mt * 16 + row;
        if (node0 < N_NODES) {
            float2 o;
            o.x = fmaxf((ch[0] + cc[0]) + bb0, 0.f);
            o.y = fmaxf((ch[1] + cc[1]) + bb1, 0.f);
            *(float2*)(hout + (size_t)node0 * HSTRIDE + col) = o;
        }
        int node1 = node0 + 8;
        if (node1 < N_NODES) {
            float2 o;
            o.x = fmaxf((ch[2] + cc[2]) + bb0, 0.f);
            o.y = fmaxf((ch[3] + cc[3]) + bb1, 0.f);
            *(float2*)(hout + (size_t)node1 * HSTRIDE + col) = o;
        }
        __syncthreads();
    }
}

// ---------------- tensorized readout: partial[b][k] = sum relu(h@Rc + Rb)[k] ----------------
__global__ __launch_bounds__(RTHREADS)
void readout_kernel(const float* __restrict__ Rb) {
    __shared__ uint32_t sR[2 * IMGWR];   // [hi | lo], single buffer
    int tid = threadIdx.x, w = tid >> 5, lane = tid & 31;
    int base = blockIdx.x * BM;

    uint32_t Bh[RNKT][2], Bl[RNKT][2];
#pragma unroll
    for (int kt = 0; kt < RNKT; ++kt)
#pragma unroll
        for (int r = 0; r < 2; ++r) {
            int idx = ((w * RNKT + kt) * 2 + r) * 32 + lane;
            Bh[kt][r] = g_Rfhi[idx];
            Bl[kt][r] = g_Rflo[idx];
        }
    int col = w * 8 + (lane & 3) * 2;
    float rb0 = __ldg(&Rb[col]), rb1 = __ldg(&Rb[col + 1]);

    // zero pad words (cols 72..79) once, both images
    if (tid >= 288 && tid < 288 + 128) {
        int t2 = tid - 288;
        int img = t2 >> 6, r = (t2 >> 2) & 15, wd = 36 + (t2 & 3);
        sR[img * IMGWR + r * SHR + wd] = 0;
    }

    const bool doFill = tid < 288;
    const int fr = tid / 18, fq = tid % 18;
    const int lrow = (lane & 7) + 8 * ((lane >> 3) & 1);
    const int loff = (lrow * SHR + ((lane >> 4) & 1) * 4) * 4;
    const uint32_t sbase = (uint32_t)__cvta_generic_to_shared(sR);

    float s0 = 0.f, s1 = 0.f;
#pragma unroll 1
    for (int mt = 0; mt < BMT; ++mt) {
        __syncthreads();
        if (doFill) {
            int node = base + mt * 16 + fr;
            if (node > N_NODES - 1) node = N_NODES - 1;
            float4 v = *(const float4*)(g_h[0] + (size_t)node * HSTRIDE + 4 * fq);
            int sb = fr * SHR + 2 * fq;
            __half2 h01 = __float22half2_rn(make_float2(v.x, v.y));
            __half2 h23 = __float22half2_rn(make_float2(v.z, v.w));
            float2 f01 = __half22float2(h01);
            float2 f23 = __half22float2(h23);
            __half2 l01 = __float22half2_rn(make_float2(v.x - f01.x, v.y - f01.y));
            __half2 l23 = __float22half2_rn(make_float2(v.z - f23.x, v.w - f23.y));
            *(uint2*)(sR + sb)          = make_uint2(h2u(h01), h2u(h23));
            *(uint2*)(sR + IMGWR + sb)  = make_uint2(h2u(l01), h2u(l23));
        }
        __syncthreads();

        const uint32_t ahi = sbase + loff;
        const uint32_t alo = ahi + IMGWR * 4;
        float ch[4] = {0.f, 0.f, 0.f, 0.f};
        float cc[4] = {0.f, 0.f, 0.f, 0.f};
#pragma unroll
        for (int kt = 0; kt < RNKT; ++kt) {
            uint32_t A[4], L[4];
            LDSM4(A, ahi + kt * 32);
            LDSM4(L, alo + kt * 32);
            MMA16(ch, A[0], A[1], A[2], A[3], Bh[kt][0], Bh[kt][1]);
            MMA16(cc, A[0], A[1], A[2], A[3], Bl[kt][0], Bl[kt][1]);
            MMA16(cc, L[0], L[1], L[2], L[3], Bh[kt][0], Bh[kt][1]);
        }

        int row = lane >> 2;
        int node0 = base + mt * 16 + row;
        if (node0 < N_NODES) {
            s0 += fmaxf(ch[0] + cc[0] + rb0, 0.f);
            s1 += fmaxf(ch[1] + cc[1] + rb1, 0.f);
        }
        if (node0 + 8 < N_NODES) {
            s0 += fmaxf(ch[2] + cc[2] + rb0, 0.f);
            s1 += fmaxf(ch[3] + cc[3] + rb1, 0.f);
        }
    }

    // reduce across the 8 row-groups (lane bits 2..4)
#pragma unroll
    for (int m = 4; m <= 16; m <<= 1) {
        s0 += __shfl_xor_sync(0xFFFFFFFFu, s0, m);
        s1 += __shfl_xor_sync(0xFFFFFFFFu, s1, m);
    }
    if ((lane >> 2) == 0) {
        g_partial[blockIdx.x * 128 + col] = s0;
        g_partial[blockIdx.x * 128 + col + 1] = s1;
    }
}

// ---------------- deterministic reduction + head MLP ----------------
__global__ void final_kernel(const float* __restrict__ S1w, const float* __restrict__ S1b,
                             const float* __restrict__ S2w, const float* __restrict__ S2b,
                             const float* __restrict__ Hw,  const float* __restrict__ Hb,
                             const float* __restrict__ Ow,  const float* __restrict__ Ob,
                             float* __restrict__ out) {
    __shared__ float fm[128], av[128], bv[100], cv[100];
    int t = threadIdx.x;
    float s = 0.f;
    for (int b = 0; b < NBLK; ++b) s += g_partial[b * 128 + t];
    fm[t] = s;
    __syncthreads();
    float v = S1b[t];
    for (int p = 0; p < 128; ++p) v += fm[p] * S1w[p * 128 + t];
    av[t] = fmaxf(v, 0.f);
    __syncthreads();
    if (t < 100) {
        v = S2b[t];
        for (int p = 0; p < 128; ++p) v += av[p] * S2w[p * 100 + t];
        bv[t] = v;
    }
    __syncthreads();
    if (t < 100) {
        v = Hb[t];
        for (int p = 0; p < 100; ++p) v += bv[p] * Hw[p * 100 + t];
        cv[t] = fmaxf(v, 0.f);
    }
    __syncthreads();
    if (t == 0) {
        v = Ob[0];
        for (int p = 0; p < 100; ++p) v += cv[p] * Ow[p];
        out[0] = v;
    }
}

extern "C" void kernel_launch(void* const* d_in, const int* in_sizes, int n_in,
                              void* d_out, int out_size) {
    const float* h   = (const float*)d_in[0];
    const float* ef  = (const float*)d_in[1];
    const int*   nbr = (const int*)d_in[2];
    const float* Vw  = (const float*)d_in[3];
    const float* Vb  = (const float*)d_in[4];
    const float* Ew  = (const float*)d_in[5];
    const float* Eb  = (const float*)d_in[6];
    const float* Uw  = (const float*)d_in[7];
    const float* Ub  = (const float*)d_in[8];
    const float* Rw  = (const float*)d_in[9];
    const float* Rb  = (const float*)d_in[10];
    const float* S1w = (const float*)d_in[11];
    const float* S1b = (const float*)d_in[12];
    const float* S2w = (const float*)d_in[13];
    const float* S2b = (const float*)d_in[14];
    const float* Hw  = (const float*)d_in[15];
    const float* Hb  = (const float*)d_in[16];
    const float* Ow  = (const float*)d_in[17];
    const float* Ob  = (const float*)d_in[18];
    float* out = (float*)d_out;

    setup_kernel<<<EDGE_BLKS + INIT_BLKS + PREP_BLKS, 256>>>(ef, Ew, Eb, nbr, h, Vw, Uw);
    prep2_kernel<<<40, 256>>>(Vb, Uw, Ub, Rw);

    int src = 0;
    for (int r = 0; r < T_ROUNDS; ++r) {
        for (int j = 0; j < DEG; ++j) {
            step_kernel<<<NBLK, THREADS>>>(j, src);
            src ^= 1;
        }
    }
    // 48 steps (even) -> final state in g_h[0]
    readout_kernel<<<NBLK, RTHREADS>>>(Rb);
    final_kernel<<<1, 128>>>(S1w, S1b, S2w, S2b, Hw, Hb, Ow, Ob, out);
}

// round 17
// speedup vs baseline: 1.5386x; 1.2985x over previous
#include <cuda_runtime.h>
#include <cuda_fp16.h>
#include <cstdint>

#define N_NODES 200000
#define DEG 16
#define T_ROUNDS 3
#define HDIM 70
#define HCW 72              // combined h row: 72 words = [36 hi half2 | 36 lo half2] = 288 B
#define NKT 10              // step K padded to 160 = 10 * 16
#define NB 72
#define WARPS 9
#define THREADS 288
#define BMT 29
#define BM (BMT * 16)       // 464
#define NBLK 432            // one wave
#define SH 84               // step A smem row stride in words (336 B)
#define IMGW (16 * SH)

// readout
#define RNKT 5
#define RTHREADS 512
#define RWARPS 16
#define SHR 44
#define IMGWR (16 * SHR)

// fused setup partition
#define EDGE_BLKS 12500     // N*DEG / 256
#define INIT_BLKS 56250     // N*HCW / 256
#define PREP_BLKS 45        // 160*72 / 256

// ---------------- device scratch ----------------
__device__ uint32_t g_hc[2][N_NODES * HCW];      // combined hi|lo fp16 node state
__device__ uint32_t g_meHL[DEG][N_NODES * 8];    // per (j,node): [hi x3,0, lo x3,0]
__device__ int      g_nbrT[DEG][N_NODES];
__device__ float    g_Wtmp[160 * NB];
__device__ uint32_t g_Bfhi[WARPS * NKT * 2 * 32];
__device__ uint32_t g_Bflo[WARPS * NKT * 2 * 32];
__device__ uint32_t g_Rfhi[RWARPS * RNKT * 2 * 32];
__device__ uint32_t g_Rflo[RWARPS * RNKT * 2 * 32];
__device__ float    g_btot[NB];
__device__ float    g_partial[NBLK * 128];

// ---------------- helpers ----------------
__device__ __forceinline__ uint32_t pack_h2(__half a, __half b) {
    __half2 t = __halves2half2(a, b);
    return *(uint32_t*)&t;
}
__device__ __forceinline__ uint32_t h2u(__half2 h) { return *(uint32_t*)&h; }

#define MMA16(C,a0,a1,a2,a3,b0,b1)                                           \
    asm volatile("mma.sync.aligned.m16n8k16.row.col.f32.f16.f16.f32 "        \
        "{%0,%1,%2,%3}, {%4,%5,%6,%7}, {%8,%9}, {%0,%1,%2,%3};"              \
        : "+f"(C[0]), "+f"(C[1]), "+f"(C[2]), "+f"(C[3])                     \
        : "r"(a0), "r"(a1), "r"(a2), "r"(a3), "r"(b0), "r"(b1))

#define LDSM4(R, addr)                                                       \
    asm volatile("ldmatrix.sync.aligned.m8n8.x4.shared.b16 {%0,%1,%2,%3}, [%4];" \
        : "=r"((R)[0]), "=r"((R)[1]), "=r"((R)[2]), "=r"((R)[3]) : "r"(addr))

__device__ __forceinline__ void cp16(uint32_t dst, const void* src) {
    asm volatile("cp.async.cg.shared.global [%0], [%1], 16;" :: "r"(dst), "l"(src));
}
#define CP_COMMIT() asm volatile("cp.async.commit_group;" ::: "memory")
#define CP_WAIT0()  asm volatile("cp.async.wait_group 0;" ::: "memory")

// ---------------- fused setup: edge msgs + init h(hi|lo) + folded W ----------------
__global__ void setup_kernel(const float* __restrict__ ef,
                             const float* __restrict__ Ew,
                             const float* __restrict__ Eb,
                             const int* __restrict__ nbr,
                             const float* __restrict__ h,
                             const float* __restrict__ Vw,
                             const float* __restrict__ Uw) {
    int b = blockIdx.x;
    if (b < EDGE_BLKS) {
        int i = b * 256 + threadIdx.x;
        if (i >= N_NODES * DEG) return;
        int node = i / DEG, j = i % DEG;
        float e[6], s[6];
#pragma unroll
        for (int d = 0; d < 6; ++d) e[d] = ef[i * 6 + d];
#pragma unroll
        for (int c = 0; c < 6; ++c) {
            float v = __ldg(&Eb[c]);
#pragma unroll
            for (int d = 0; d < 6; ++d) v += e[d] * __ldg(&Ew[d * 6 + c]);
            s[c] = v;
        }
        uint32_t* o = g_meHL[j] + (size_t)node * 8;
#pragma unroll
        for (int p = 0; p < 3; ++p) {
            __half h0 = __float2half_rn(s[2 * p]), h1 = __float2half_rn(s[2 * p + 1]);
            o[p] = pack_h2(h0, h1);
            o[4 + p] = pack_h2(__float2half_rn(s[2 * p] - __half2float(h0)),
                               __float2half_rn(s[2 * p + 1] - __half2float(h1)));
        }
        o[3] = 0; o[7] = 0;
        g_nbrT[j][node] = nbr[i];
    } else if (b < EDGE_BLKS + INIT_BLKS) {
        int i = (b - EDGE_BLKS) * 256 + threadIdx.x;   // over N_NODES * HCW words
        int node = i / HCW, w = i % HCW;
        int k2 = (w < 36) ? w : (w - 36);
        int f0 = 2 * k2;
        float x0 = (f0 < HDIM) ? h[(size_t)node * HDIM + f0] : 0.f;
        float x1 = (f0 + 1 < HDIM) ? h[(size_t)node * HDIM + f0 + 1] : 0.f;
        __half h0 = __float2half_rn(x0), h1 = __float2half_rn(x1);
        uint32_t val;
        if (w < 36) val = pack_h2(h0, h1);
        else        val = pack_h2(__float2half_rn(x0 - __half2float(h0)),
                                  __float2half_rn(x1 - __half2float(h1)));
        g_hc[0][i] = val;
    } else {
        int i = (b - EDGE_BLKS - INIT_BLKS) * 256 + threadIdx.x;
        int k = i / NB, n = i % NB;
        float w = 0.f;
        if (n < HDIM) {
            if (k < 70) {
                w = Uw[k * HDIM + n];
            } else if (k >= 72 && k < 142) {
                int p = k - 72;
                float s = 0.f;
                for (int q = 0; q < 70; ++q) s += Vw[p * 70 + q] * Uw[(70 + q) * HDIM + n];
                w = s;
            } else if (k >= 144 && k < 150) {
                w = Uw[(140 + (k - 144)) * HDIM + n];
            }
        }
        g_Wtmp[i] = w;
    }
}

// ---------------- prep2: fragment images + bias ----------------
__global__ void prep2_kernel(const float* __restrict__ Vb,
                             const float* __restrict__ Uw, const float* __restrict__ Ub,
                             const float* __restrict__ Rw) {
    int stride = gridDim.x * blockDim.x;
    int tid0 = blockIdx.x * blockDim.x + threadIdx.x;
    for (int idx = tid0; idx < WARPS * NKT * 2 * 32; idx += stride) {
        int lane = idx & 31;
        int t = idx >> 5;
        int r = t & 1; t >>= 1;
        int kt = t % NKT;
        int w = t / NKT;
        int k0 = kt * 16 + (lane & 3) * 2 + 8 * r;
        int n = w * 8 + (lane >> 2);
        float v0 = g_Wtmp[k0 * NB + n];
        float v1 = g_Wtmp[(k0 + 1) * NB + n];
        __half h0 = __float2half_rn(v0), h1 = __float2half_rn(v1);
        g_Bfhi[idx] = pack_h2(h0, h1);
        g_Bflo[idx] = pack_h2(__float2half_rn(v0 - __half2float(h0)),
                              __float2half_rn(v1 - __half2float(h1)));
    }
    for (int idx = tid0; idx < RWARPS * RNKT * 2 * 32; idx += stride) {
        int lane = idx & 31;
        int t = idx >> 5;
        int r = t & 1; t >>= 1;
        int kt = t % RNKT;
        int w = t / RNKT;
        int k0 = kt * 16 + (lane & 3) * 2 + 8 * r;
        int n = w * 8 + (lane >> 2);
        float v0 = (k0 < HDIM) ? (Rw[k0 * 128 + n] + Rw[(70 + k0) * 128 + n]) : 0.f;
        float v1 = (k0 + 1 < HDIM) ? (Rw[(k0 + 1) * 128 + n] + Rw[(71 + k0) * 128 + n]) : 0.f;
        __half h0 = __float2half_rn(v0), h1 = __float2half_rn(v1);
        g_Rfhi[idx] = pack_h2(h0, h1);
        g_Rflo[idx] = pack_h2(__float2half_rn(v0 - __half2float(h0)),
                              __float2half_rn(v1 - __half2float(h1)));
    }
    for (int k = tid0; k < NB; k += stride) {
        float v = 0.f;
        if (k < HDIM) {
            v = Ub[k];
            for (int q = 0; q < 70; ++q) v += Vb[q] * Uw[(70 + q) * HDIM + k];
        }
        g_btot[k] = v;
    }
}

// ---------------- fill chunk via cp.async: 608 16B-chunks per m-tile ----------------
// chunk c: r = c/38, t = c%38, img = t/19, u = t%19; u<9 self, u<18 gather, u==18 me
__device__ __forceinline__ void cp_chunk(uint32_t sbase, const uint32_t* __restrict__ hin,
                                         const uint32_t* __restrict__ mej,
                                         const int* __restrict__ sg,
                                         int base, int mt, int r, int img, int u) {
    int node = base + mt * 16 + r;
    if (node > N_NODES - 1) node = N_NODES - 1;
    const uint32_t* srcp;
    uint32_t dstw = (uint32_t)(img * IMGW + r * SH);
    if (u < 9) {
        srcp = hin + (size_t)node * HCW + img * 36 + u * 4;
        dstw += u * 4;
    } else if (u < 18) {
        int gi = sg[mt * 16 + r];
        srcp = hin + (size_t)gi * HCW + img * 36 + (u - 9) * 4;
        dstw += 36 + (u - 9) * 4;
    } else {
        srcp = mej + (size_t)node * 8 + img * 4;
        dstw += 72;
    }
    cp16(sbase + dstw * 4, srcp);
}

// ---------------- one MP step (cp.async fill + fp16 3-term MMA) ----------------
__global__ __launch_bounds__(THREADS, 3)
void step_kernel(int j, int src) {
    __shared__ __align__(16) uint32_t sA[2][2 * IMGW];
    __shared__ int s_gidx[BM];

    const uint32_t* __restrict__ hin = g_hc[src];
    uint32_t* __restrict__ hout = g_hc[src ^ 1];
    const int* __restrict__ nbrj = g_nbrT[j];
    const uint32_t* __restrict__ mej = g_meHL[j];
    int tid = threadIdx.x, w = tid >> 5, lane = tid & 31;
    int base = blockIdx.x * BM;

    uint32_t Bhi[NKT][2], Blo[NKT][2];
#pragma unroll
    for (int kt = 0; kt < NKT; ++kt)
#pragma unroll
        for (int r = 0; r < 2; ++r) {
            int idx = ((w * NKT + kt) * 2 + r) * 32 + lane;
            Bhi[kt][r] = g_Bfhi[idx];
            Blo[kt][r] = g_Bflo[idx];
        }
    int col = w * 8 + (lane & 3) * 2;
    float bb0 = g_btot[col], bb1 = g_btot[col + 1];

    for (int i = tid; i < BM; i += THREADS) {
        int node = base + i;
        if (node > N_NODES - 1) node = N_NODES - 1;
        s_gidx[i] = __ldg(&nbrj[node]);
    }
    // zero pad words (halves 152..159) once per buffer/image/row
    if (tid < 256) {
        int buf = tid >> 7, img = (tid >> 6) & 1, r = (tid >> 2) & 15;
        sA[buf][img * IMGW + r * SH + 76 + (tid & 3)] = 0;
    }
    __syncthreads();

    // per-thread chunk descriptors: c0 = tid, c1 = tid+288, c2 = tid+576 (tid<32)
    const int c0 = tid, c1 = tid + THREADS;
    const int r0 = c0 / 38, t0 = c0 - r0 * 38, i0 = t0 / 19, u0 = t0 - i0 * 19;
    const int r1 = c1 / 38, t1 = c1 - r1 * 38, i1 = t1 / 19, u1 = t1 - i1 * 19;
    const bool has2 = (tid < 608 - 2 * THREADS);   // 32 threads
    const int c2 = tid + 2 * THREADS;
    const int r2 = c2 / 38, t2 = c2 - r2 * 38, i2 = t2 / 19, u2 = t2 - i2 * 19;

    const uint32_t sb0 = (uint32_t)__cvta_generic_to_shared(sA[0]);
    const uint32_t sb1 = (uint32_t)__cvta_generic_to_shared(sA[1]);

    // prologue: fill tile 0
    cp_chunk(sb0, hin, mej, s_gidx, base, 0, r0, i0, u0);
    cp_chunk(sb0, hin, mej, s_gidx, base, 0, r1, i1, u1);
    if (has2) cp_chunk(sb0, hin, mej, s_gidx, base, 0, r2, i2, u2);
    CP_COMMIT();
    CP_WAIT0();
    __syncthreads();

    const int lrow = (lane & 7) + 8 * ((lane >> 3) & 1);
    const int loff = (lrow * SH + ((lane >> 4) & 1) * 4) * 4;

#pragma unroll 1
    for (int mt = 0; mt < BMT; ++mt) {
        // (1) fire async fill of tile mt+1 into the other buffer
        if (mt < BMT - 1) {
            uint32_t nb = (mt & 1) ? sb0 : sb1;
            cp_chunk(nb, hin, mej, s_gidx, base, mt + 1, r0, i0, u0);
            cp_chunk(nb, hin, mej, s_gidx, base, mt + 1, r1, i1, u1);
            if (has2) cp_chunk(nb, hin, mej, s_gidx, base, mt + 1, r2, i2, u2);
            CP_COMMIT();
        }

        // (2) compute tile mt
        const uint32_t ahi = ((mt & 1) ? sb1 : sb0) + loff;
        const uint32_t alo = ahi + IMGW * 4;
        float ch[4] = {0.f, 0.f, 0.f, 0.f};
        float cc[4] = {0.f, 0.f, 0.f, 0.f};
#pragma unroll
        for (int kt = 0; kt < NKT; ++kt) {
            uint32_t A[4], L[4];
            LDSM4(A, ahi + kt * 32);
            LDSM4(L, alo + kt * 32);
            MMA16(ch, A[0], A[1], A[2], A[3], Bhi[kt][0], Bhi[kt][1]);
            MMA16(cc, A[0], A[1], A[2], A[3], Blo[kt][0], Blo[kt][1]);
            MMA16(cc, L[0], L[1], L[2], L[3], Bhi[kt][0], Bhi[kt][1]);
        }

        // (3) epilogue: bias + relu, split hi/lo, store combined row words
        int row = lane >> 2;
        int node0 = base + mt * 16 + row;
        int cw = col >> 1;
        if (node0 < N_NODES) {
            float ox = fmaxf(ch[0] + cc[0] + bb0, 0.f);
            float oy = fmaxf(ch[1] + cc[1] + bb1, 0.f);
            __half2 hh = __float22half2_rn(make_float2(ox, oy));
            float2 f = __half22float2(hh);
            __half2 ll = __float22half2_rn(make_float2(ox - f.x, oy - f.y));
            hout[(size_t)node0 * HCW + cw] = h2u(hh);
            hout[(size_t)node0 * HCW + 36 + cw] = h2u(ll);
        }
        int node1 = node0 + 8;
        if (node1 < N_NODES) {
            float ox = fmaxf(ch[2] + cc[2] + bb0, 0.f);
            float oy = fmaxf(ch[3] + cc[3] + bb1, 0.f);
            __half2 hh = __float22half2_rn(make_float2(ox, oy));
            float2 f = __half22float2(hh);
            __half2 ll = __float22half2_rn(make_float2(ox - f.x, oy - f.y));
            hout[(size_t)node1 * HCW + cw] = h2u(hh);
            hout[(size_t)node1 * HCW + 36 + cw] = h2u(ll);
        }

        // (4) drain this thread's async copies, then block-wide visibility
        if (mt < BMT - 1) CP_WAIT0();
        __syncthreads();
    }
}

// ---------------- tensorized readout (raw-copy fill from split h) ----------------
__global__ __launch_bounds__(RTHREADS)
void readout_kernel(const float* __restrict__ Rb) {
    __shared__ __align__(16) uint32_t sR[2 * IMGWR];
    int tid = threadIdx.x, w = tid >> 5, lane = tid & 31;
    int base = blockIdx.x * BM;

    uint32_t Bh[RNKT][2], Bl[RNKT][2];
#pragma unroll
    for (int kt = 0; kt < RNKT; ++kt)
#pragma unroll
        for (int r = 0; r < 2; ++r) {
            int idx = ((w * RNKT + kt) * 2 + r) * 32 + lane;
            Bh[kt][r] = g_Rfhi[idx];
            Bl[kt][r] = g_Rflo[idx];
        }
    int col = w * 8 + (lane & 3) * 2;
    float rb0 = __ldg(&Rb[col]), rb1 = __ldg(&Rb[col + 1]);

    // zero pad words (halves 72..79), both images
    if (tid >= 288 && tid < 288 + 128) {
        int t2 = tid - 288;
        int img = t2 >> 6, r = (t2 >> 2) & 15, wd = 36 + (t2 & 3);
        sR[img * IMGWR + r * SHR + wd] = 0;
    }

    const bool doFill = tid < 288;
    const int fr = tid / 18, ft = tid % 18;
    const int fimg = ft / 9, fu = ft % 9;
    const int lrow = (lane & 7) + 8 * ((lane >> 3) & 1);
    const int loff = (lrow * SHR + ((lane >> 4) & 1) * 4) * 4;
    const uint32_t sbase = (uint32_t)__cvta_generic_to_shared(sR);

    float s0 = 0.f, s1 = 0.f;
#pragma unroll 1
    for (int mt = 0; mt < BMT; ++mt) {
        __syncthreads();
        if (doFill) {
            int node = base + mt * 16 + fr;
            if (node > N_NODES - 1) node = N_NODES - 1;
            uint4 v = *(const uint4*)(g_hc[0] + (size_t)node * HCW + fimg * 36 + fu * 4);
            *(uint4*)(sR + fimg * IMGWR + fr * SHR + fu * 4) = v;
        }
        __syncthreads();

        const uint32_t ahi = sbase + loff;
        const uint32_t alo = ahi + IMGWR * 4;
        float ch[4] = {0.f, 0.f, 0.f, 0.f};
        float cc[4] = {0.f, 0.f, 0.f, 0.f};
#pragma unroll
        for (int kt = 0; kt < RNKT; ++kt) {
            uint32_t A[4], L[4];
            LDSM4(A, ahi + kt * 32);
            LDSM4(L, alo + kt * 32);
            MMA16(ch, A[0], A[1], A[2], A[3], Bh[kt][0], Bh[kt][1]);
            MMA16(cc, A[0], A[1], A[2], A[3], Bl[kt][0], Bl[kt][1]);
            MMA16(cc, L[0], L[1], L[2], L[3], Bh[kt][0], Bh[kt][1]);
        }

        int row = lane >> 2;
        int node0 = base + mt * 16 + row;
        if (node0 < N_NODES) {
            s0 += fmaxf(ch[0] + cc[0] + rb0, 0.f);
            s1 += fmaxf(ch[1] + cc[1] + rb1, 0.f);
        }
        if (node0 + 8 < N_NODES) {
            s0 += fmaxf(ch[2] + cc[2] + rb0, 0.f);
            s1 += fmaxf(ch[3] + cc[3] + rb1, 0.f);
        }
    }

#pragma unroll
    for (int m = 4; m <= 16; m <<= 1) {
        s0 += __shfl_xor_sync(0xFFFFFFFFu, s0, m);
        s1 += __shfl_xor_sync(0xFFFFFFFFu, s1, m);
    }
    if ((lane >> 2) == 0) {
        g_partial[blockIdx.x * 128 + col] = s0;
        g_partial[blockIdx.x * 128 + col + 1] = s1;
    }
}

// ---------------- deterministic reduction + head MLP ----------------
__global__ void final_kernel(const float* __restrict__ S1w, const float* __restrict__ S1b,
                             const float* __restrict__ S2w, const float* __restrict__ S2b,
                             const float* __restrict__ Hw,  const float* __restrict__ Hb,
                             const float* __restrict__ Ow,  const float* __restrict__ Ob,
                             float* __restrict__ out) {
    __shared__ float fm[128], av[128], bv[100], cv[100];
    int t = threadIdx.x;
    float s = 0.f;
    for (int b = 0; b < NBLK; ++b) s += g_partial[b * 128 + t];
    fm[t] = s;
    __syncthreads();
    float v = S1b[t];
    for (int p = 0; p < 128; ++p) v += fm[p] * S1w[p * 128 + t];
    av[t] = fmaxf(v, 0.f);
    __syncthreads();
    if (t < 100) {
        v = S2b[t];
        for (int p = 0; p < 128; ++p) v += av[p] * S2w[p * 100 + t];
        bv[t] = v;
    }
    __syncthreads();
    if (t < 100) {
        v = Hb[t];
        for (int p = 0; p < 100; ++p) v += bv[p] * Hw[p * 100 + t];
        cv[t] = fmaxf(v, 0.f);
    }
    __syncthreads();
    if (t == 0) {
        v = Ob[0];
        for (int p = 0; p < 100; ++p) v += cv[p] * Ow[p];
        out[0] = v;
    }
}

extern "C" void kernel_launch(void* const* d_in, const int* in_sizes, int n_in,
                              void* d_out, int out_size) {
    const float* h   = (const float*)d_in[0];
    const float* ef  = (const float*)d_in[1];
    const int*   nbr = (const int*)d_in[2];
    const float* Vw  = (const float*)d_in[3];
    const float* Vb  = (const float*)d_in[4];
    const float* Ew  = (const float*)d_in[5];
    const float* Eb  = (const float*)d_in[6];
    const float* Uw  = (const float*)d_in[7];
    const float* Ub  = (const float*)d_in[8];
    const float* Rw  = (const float*)d_in[9];
    const float* Rb  = (const float*)d_in[10];
    const float* S1w = (const float*)d_in[11];
    const float* S1b = (const float*)d_in[12];
    const float* S2w = (const float*)d_in[13];
    const float* S2b = (const float*)d_in[14];
    const float* Hw  = (const float*)d_in[15];
    const float* Hb  = (const float*)d_in[16];
    const float* Ow  = (const float*)d_in[17];
    const float* Ob  = (const float*)d_in[18];
    float* out = (float*)d_out;

    setup_kernel<<<EDGE_BLKS + INIT_BLKS + PREP_BLKS, 256>>>(ef, Ew, Eb, nbr, h, Vw, Uw);
    prep2_kernel<<<40, 256>>>(Vb, Uw, Ub, Rw);

    int src = 0;
    for (int r = 0; r < T_ROUNDS; ++r) {
        for (int j = 0; j < DEG; ++j) {
            step_kernel<<<NBLK, THREADS>>>(j, src);
            src ^= 1;
        }
    }
    // 48 steps (even) -> final state in g_hc[0]
    readout_kernel<<<NBLK, RTHREADS>>>(Rb);
    final_kernel<<<1, 128>>>(S1w, S1b, S2w, S2b, Hw, Hb, Ow, Ob, out);
}